// round 4
// baseline (speedup 1.0000x reference)
#include <cuda_runtime.h>
#include <cuda_bf16.h>
#include <cstdint>

#define B_ROWS 32768
#define C_COLS 1000
#define C_PAD  1024
#define FDIM   256

#define BM 32
#define BN 64
#define NCHUNKS (C_PAD / BN)     // 16
#define PADK 264                 // halves per smem row (8-half pad -> conflict-free ldmatrix)
#define ROWB (PADK * 2)          // 528 bytes per smem row

// SMEM layout (bytes)
#define OFF_AS   0
#define SZ_AS    (BM * ROWB)                  // 16896
#define OFF_BS   (OFF_AS + SZ_AS)             // 16896
#define SZ_BSBUF (BN * ROWB)                  // 33792
#define SZ_BS    (2 * SZ_BSBUF)               // 67584
#define OFF_DIST (OFF_BS + SZ_BS)             // 84480
#define SZ_DIST  (BM * C_COLS * 4)            // 128000
#define OFF_RSUM (OFF_DIST + SZ_DIST)         // 212480
#define SMEM_TOTAL (OFF_RSUM + BM * 4)        // 212608

// scratch (device globals: no allocation allowed)
__device__ __nv_bfloat16 g_fn[(size_t)B_ROWS * FDIM];
__device__ __nv_bfloat16 g_pn[(size_t)C_PAD * FDIM];

#define CP_ASYNC16(dst, src) \
    asm volatile("cp.async.cg.shared.global [%0], [%1], 16;\n" :: "r"(dst), "l"(src))
#define CP_COMMIT() asm volatile("cp.async.commit_group;\n")
#define CP_WAIT(n)  asm volatile("cp.async.wait_group %0;\n" :: "n"(n))

// ---------------------------------------------------------------------------
// Row L2-normalize fp32 -> bf16, padding rows >= nreal with zeros.
// One warp per row; blockDim = 256 (8 rows / block).
// ---------------------------------------------------------------------------
__device__ __forceinline__ void normalize_row(const float* __restrict__ in,
                                              __nv_bfloat16* __restrict__ out,
                                              int nreal, int npad) {
    int row  = blockIdx.x * 8 + (threadIdx.x >> 5);
    int lane = threadIdx.x & 31;
    if (row >= npad) return;
    uint2* orow = (uint2*)(out + (size_t)row * FDIM);   // 4 bf16 per uint2
    if (row >= nreal) {
        uint2 z = make_uint2(0u, 0u);
        orow[lane] = z; orow[lane + 32] = z;
        return;
    }
    const float4* irow = (const float4*)(in + (size_t)row * FDIM);
    float4 v0 = irow[lane];
    float4 v1 = irow[lane + 32];
    float ss = v0.x*v0.x + v0.y*v0.y + v0.z*v0.z + v0.w*v0.w
             + v1.x*v1.x + v1.y*v1.y + v1.z*v1.z + v1.w*v1.w;
    #pragma unroll
    for (int o = 16; o > 0; o >>= 1) ss += __shfl_xor_sync(0xFFFFFFFFu, ss, o);
    float inv = 1.0f / fmaxf(sqrtf(ss), 1e-12f);

    __nv_bfloat162 p0 = __floats2bfloat162_rn(v0.x*inv, v0.y*inv);
    __nv_bfloat162 p1 = __floats2bfloat162_rn(v0.z*inv, v0.w*inv);
    __nv_bfloat162 p2 = __floats2bfloat162_rn(v1.x*inv, v1.y*inv);
    __nv_bfloat162 p3 = __floats2bfloat162_rn(v1.z*inv, v1.w*inv);
    uint2 u0, u1;
    u0.x = *(uint32_t*)&p0; u0.y = *(uint32_t*)&p1;
    u1.x = *(uint32_t*)&p2; u1.y = *(uint32_t*)&p3;
    orow[lane] = u0; orow[lane + 32] = u1;
}

__global__ void normalize_feats_kernel(const float* __restrict__ in) {
    normalize_row(in, g_fn, B_ROWS, B_ROWS);
}
__global__ void normalize_protos_kernel(const float* __restrict__ in) {
    normalize_row(in, g_pn, C_COLS, C_PAD);
}

// ---------------------------------------------------------------------------
// Main fused kernel: 32-row strip x full C. bf16 mma.sync GEMM, dist kept in
// SMEM, row-mean fused, single output write.
// ---------------------------------------------------------------------------
__global__ __launch_bounds__(256, 1)
void dismax_main_kernel(const float* __restrict__ dscale,
                        const float* __restrict__ dtemp,
                        float* __restrict__ out) {
    extern __shared__ char smem[];
    float* dist   = (float*)(smem + OFF_DIST);   // [BM][C_COLS]
    float* rowsum = (float*)(smem + OFF_RSUM);   // [BM]

    const int tid  = threadIdx.x;
    const int lane = tid & 31;
    const int warp = tid >> 5;
    const int wm   = warp >> 2;    // 0..1  (16 rows each)
    const int wn   = warp & 3;     // 0..3  (16 cols each within BN=64)
    const int rowBase = blockIdx.x * BM;

    if (tid < BM) rowsum[tid] = 0.0f;

    const uint32_t AsAddr = (uint32_t)__cvta_generic_to_shared(smem + OFF_AS);
    const uint32_t BsAddr = (uint32_t)__cvta_generic_to_shared(smem + OFF_BS);

    // ---- A tile (32x256) via cp.async, grouped with B chunk 0 ----
    {
        const __nv_bfloat16* gA = g_fn + (size_t)rowBase * FDIM;
        #pragma unroll
        for (int i = 0; i < 4; i++) {
            int f = tid + i * 256;          // 1024 x 16B
            int r = f >> 5, c16 = f & 31;
            CP_ASYNC16(AsAddr + r * ROWB + c16 * 16, gA + r * FDIM + c16 * 8);
        }
    }
    auto issueB = [&](int chunk, int buf) {
        const __nv_bfloat16* src = g_pn + (size_t)chunk * BN * FDIM;
        const uint32_t base = BsAddr + buf * SZ_BSBUF;
        #pragma unroll
        for (int i = 0; i < 8; i++) {
            int f = tid + i * 256;          // 2048 x 16B
            int r = f >> 5, c16 = f & 31;
            CP_ASYNC16(base + r * ROWB + c16 * 16, src + r * FDIM + c16 * 8);
        }
    };
    issueB(0, 0);
    CP_COMMIT();                             // group 0 = A + B0

    float c[2][4] = {};
    float sumlo = 0.0f, sumhi = 0.0f;

    // ldmatrix lane addresses.
    // A tile is [m][k] row-major -> non-trans x4 gives a0..a3 fragments.
    const uint32_t aBase = AsAddr + (wm * 16 + (lane & 15)) * ROWB + ((lane >> 4) * 8) * 2;
    // B tile is [n][k] row-major == col-major KxN operand -> NON-trans ldmatrix.
    // lanes 0-7: n0-7/k0-7 (b0 of mma0), 8-15: n0-7/k8-15 (b1 of mma0),
    // 16-23: n8-15/k0-7 (b0 of mma1), 24-31: n8-15/k8-15 (b1 of mma1).
    const uint32_t bRow  = (uint32_t)(wn * 16 + ((lane >> 4) << 3) + (lane & 7));
    const uint32_t bColB = (uint32_t)((((lane >> 3) & 1) << 3) * 2);

    for (int chunk = 0; chunk < NCHUNKS; chunk++) {
        const int buf = chunk & 1;
        if (chunk + 1 < NCHUNKS) {
            issueB(chunk + 1, (chunk + 1) & 1);
            CP_COMMIT();
            CP_WAIT(1);
        } else {
            CP_WAIT(0);
        }
        __syncthreads();

        const uint32_t bBase = BsAddr + buf * SZ_BSBUF + bRow * ROWB + bColB;
        #pragma unroll
        for (int kk = 0; kk < FDIM / 16; kk++) {
            uint32_t a0, a1, a2, a3, b0, b1, b2, b3;
            asm volatile("ldmatrix.sync.aligned.m8n8.x4.shared.b16 {%0,%1,%2,%3}, [%4];"
                         : "=r"(a0), "=r"(a1), "=r"(a2), "=r"(a3)
                         : "r"(aBase + kk * 32));
            asm volatile("ldmatrix.sync.aligned.m8n8.x4.shared.b16 {%0,%1,%2,%3}, [%4];"
                         : "=r"(b0), "=r"(b1), "=r"(b2), "=r"(b3)
                         : "r"(bBase + kk * 32));
            asm volatile("mma.sync.aligned.m16n8k16.row.col.f32.bf16.bf16.f32 "
                         "{%0,%1,%2,%3},{%4,%5,%6,%7},{%8,%9},{%0,%1,%2,%3};"
                         : "+f"(c[0][0]), "+f"(c[0][1]), "+f"(c[0][2]), "+f"(c[0][3])
                         : "r"(a0), "r"(a1), "r"(a2), "r"(a3), "r"(b0), "r"(b1));
            asm volatile("mma.sync.aligned.m16n8k16.row.col.f32.bf16.bf16.f32 "
                         "{%0,%1,%2,%3},{%4,%5,%6,%7},{%8,%9},{%0,%1,%2,%3};"
                         : "+f"(c[1][0]), "+f"(c[1][1]), "+f"(c[1][2]), "+f"(c[1][3])
                         : "r"(a0), "r"(a1), "r"(a2), "r"(a3), "r"(b2), "r"(b3));
        }

        // epilogue: cos -> dist, stash in SMEM, row-sum partials
        const int rg0 = wm * 16 + (lane >> 2);
        #pragma unroll
        for (int f = 0; f < 2; f++) {
            const int colb = chunk * BN + wn * 16 + f * 8 + (lane & 3) * 2;
            #pragma unroll
            for (int e = 0; e < 4; e++) {
                float cosv = c[f][e];
                c[f][e] = 0.0f;
                int r   = rg0 + (e >> 1) * 8;
                int col = colb + (e & 1);
                float d = sqrtf(fmaxf(1.0f - cosv, 0.0f));
                if (col < C_COLS) {
                    dist[r * C_COLS + col] = d;
                    if (e < 2) sumlo += d; else sumhi += d;
                }
            }
        }
        __syncthreads();
    }

    // reduce row sums within each lane-quad, then across warps via smem atomics
    sumlo += __shfl_xor_sync(0xFFFFFFFFu, sumlo, 1);
    sumlo += __shfl_xor_sync(0xFFFFFFFFu, sumlo, 2);
    sumhi += __shfl_xor_sync(0xFFFFFFFFu, sumhi, 1);
    sumhi += __shfl_xor_sync(0xFFFFFFFFu, sumhi, 2);
    if ((lane & 3) == 0) {
        int r = wm * 16 + (lane >> 2);
        atomicAdd(&rowsum[r],     sumlo);
        atomicAdd(&rowsum[r + 8], sumhi);
    }
    __syncthreads();

    const float sc   = fabsf(dscale[0]);
    const float invT = 1.0f / dtemp[0];
    // write: out = -sc*(dist + mean_dist)/temp, float4 stores (1000*4B rows are 16B-aligned)
    for (int idx = tid; idx < BM * (C_COLS / 4); idx += 256) {
        int r  = idx / (C_COLS / 4);
        int c4 = idx % (C_COLS / 4);
        float mean = rowsum[r] * (1.0f / (float)C_COLS);
        const float4 d4 = *(const float4*)&dist[r * C_COLS + c4 * 4];
        float4 o;
        o.x = -sc * (d4.x + mean) * invT;
        o.y = -sc * (d4.y + mean) * invT;
        o.z = -sc * (d4.z + mean) * invT;
        o.w = -sc * (d4.w + mean) * invT;
        *(float4*)&out[(size_t)(rowBase + r) * C_COLS + c4 * 4] = o;
    }
}

// ---------------------------------------------------------------------------
extern "C" void kernel_launch(void* const* d_in, const int* in_sizes, int n_in,
                              void* d_out, int out_size) {
    const float* feats  = (const float*)d_in[0];   // [32768, 256]
    const float* protos = (const float*)d_in[1];   // [1000, 256]
    const float* dscale = (const float*)d_in[2];   // [1]
    const float* dtemp  = (const float*)d_in[3];   // [1]
    float* out = (float*)d_out;                    // [32768, 1000]

    cudaFuncSetAttribute(dismax_main_kernel,
                         cudaFuncAttributeMaxDynamicSharedMemorySize, SMEM_TOTAL);

    normalize_feats_kernel<<<B_ROWS / 8, 256>>>(feats);
    normalize_protos_kernel<<<C_PAD / 8, 256>>>(protos);
    dismax_main_kernel<<<B_ROWS / BM, 256, SMEM_TOTAL>>>(dscale, dtemp, out);
}

// round 5
// speedup vs baseline: 1.9689x; 1.9689x over previous
#include <cuda_runtime.h>
#include <cuda_bf16.h>
#include <cstdint>

#define B_ROWS 32768
#define C_COLS 1000
#define C_PAD  1024
#define FDIM   256

#define BM 32            // rows per CTA
#define KC 32            // k-halves per streamed B chunk
#define NKC (FDIM / KC)  // 8 chunks
#define B_ROWB 80        // bytes per B smem row (64 data + 16 pad -> conflict-free ldmatrix)
#define A_ROWB 528       // bytes per A smem row (256 halves + 8 pad)

// SMEM layout (bytes)
#define OFF_A   0
#define SZ_A    (BM * A_ROWB)                 // 16896
#define OFF_B   (OFF_A + SZ_A)
#define SZ_BBUF (C_PAD * B_ROWB)              // 81920
#define OFF_RSUM (OFF_B + 2 * SZ_BBUF)        // 180736
#define SMEM_TOTAL (OFF_RSUM + BM * 4)        // 180864

// scratch (device globals: no allocation allowed)
__device__ __nv_bfloat16 g_fn[(size_t)B_ROWS * FDIM];
__device__ __nv_bfloat16 g_pn[(size_t)C_PAD * FDIM];

#define CP_ASYNC16(dst, src) \
    asm volatile("cp.async.cg.shared.global [%0], [%1], 16;\n" :: "r"(dst), "l"(src))
#define CP_COMMIT() asm volatile("cp.async.commit_group;\n")
#define CP_WAIT(n)  asm volatile("cp.async.wait_group %0;\n" :: "n"(n))

// ---------------------------------------------------------------------------
// Row L2-normalize fp32 -> bf16, padding rows >= nreal with zeros.
// ---------------------------------------------------------------------------
__device__ __forceinline__ void normalize_row(const float* __restrict__ in,
                                              __nv_bfloat16* __restrict__ out,
                                              int nreal, int npad) {
    int row  = blockIdx.x * 8 + (threadIdx.x >> 5);
    int lane = threadIdx.x & 31;
    if (row >= npad) return;
    uint2* orow = (uint2*)(out + (size_t)row * FDIM);
    if (row >= nreal) {
        uint2 z = make_uint2(0u, 0u);
        orow[lane] = z; orow[lane + 32] = z;
        return;
    }
    const float4* irow = (const float4*)(in + (size_t)row * FDIM);
    float4 v0 = irow[lane];
    float4 v1 = irow[lane + 32];
    float ss = v0.x*v0.x + v0.y*v0.y + v0.z*v0.z + v0.w*v0.w
             + v1.x*v1.x + v1.y*v1.y + v1.z*v1.z + v1.w*v1.w;
    #pragma unroll
    for (int o = 16; o > 0; o >>= 1) ss += __shfl_xor_sync(0xFFFFFFFFu, ss, o);
    float inv = 1.0f / fmaxf(sqrtf(ss), 1e-12f);

    __nv_bfloat162 p0 = __floats2bfloat162_rn(v0.x*inv, v0.y*inv);
    __nv_bfloat162 p1 = __floats2bfloat162_rn(v0.z*inv, v0.w*inv);
    __nv_bfloat162 p2 = __floats2bfloat162_rn(v1.x*inv, v1.y*inv);
    __nv_bfloat162 p3 = __floats2bfloat162_rn(v1.z*inv, v1.w*inv);
    uint2 u0, u1;
    u0.x = *(uint32_t*)&p0; u0.y = *(uint32_t*)&p1;
    u1.x = *(uint32_t*)&p2; u1.y = *(uint32_t*)&p3;
    orow[lane] = u0; orow[lane + 32] = u1;
}

__global__ void normalize_feats_kernel(const float* __restrict__ in) {
    normalize_row(in, g_fn, B_ROWS, B_ROWS);
}
__global__ void normalize_protos_kernel(const float* __restrict__ in) {
    normalize_row(in, g_pn, C_COLS, C_PAD);
}

// ---------------------------------------------------------------------------
// Main fused kernel: CTA = 32 rows x ALL 1024 cols. 512 threads, 16 warps
// (2 warp-rows x 8 warp-cols); warp tile 16x128 -> 16 independent mma chains.
// Accumulators double as the dist strip (no SMEM dist). B streamed in k-chunks.
// ---------------------------------------------------------------------------
__global__ __launch_bounds__(512, 1)
void dismax_main_kernel(const float* __restrict__ dscale,
                        const float* __restrict__ dtemp,
                        float* __restrict__ out) {
    extern __shared__ char smem[];
    float* rowsum = (float*)(smem + OFF_RSUM);

    const int tid  = threadIdx.x;
    const int lane = tid & 31;
    const int warp = tid >> 5;
    const int wr   = warp >> 3;     // 0..1  warp-row (16 rows)
    const int wc   = warp & 7;      // 0..7  warp-col (128 cols)
    const int rowBase = blockIdx.x * BM;

    if (tid < BM) rowsum[tid] = 0.0f;

    const uint32_t AsAddr = (uint32_t)__cvta_generic_to_shared(smem + OFF_A);
    const uint32_t BsAddr = (uint32_t)__cvta_generic_to_shared(smem + OFF_B);

    // ---- A tile (32 x 256 halves) ----
    {
        const __nv_bfloat16* gA = g_fn + (size_t)rowBase * FDIM;
        #pragma unroll
        for (int i = 0; i < 2; i++) {
            int idx = tid + i * 512;            // 1024 x 16B
            int r = idx >> 5, c16 = idx & 31;
            CP_ASYNC16(AsAddr + r * A_ROWB + c16 * 16, gA + r * FDIM + c16 * 8);
        }
    }
    auto issueB = [&](int kc, int buf) {
        const __nv_bfloat16* src = g_pn + kc * KC;     // column offset in halves
        const uint32_t base = BsAddr + buf * SZ_BBUF;
        #pragma unroll
        for (int i = 0; i < 8; i++) {
            int idx = tid + i * 512;            // 4096 x 16B (1024 rows x 64B)
            int n = idx >> 2, c16 = idx & 3;
            CP_ASYNC16(base + n * B_ROWB + c16 * 16, src + (size_t)n * FDIM + c16 * 8);
        }
    };
    issueB(0, 0);
    CP_COMMIT();                                 // group 0 = A + B0

    float c[16][4];
    #pragma unroll
    for (int j = 0; j < 16; j++)
        #pragma unroll
        for (int e = 0; e < 4; e++) c[j][e] = 0.0f;

    // ldmatrix lane addresses (non-trans; B is [n][k] == col-major KxN)
    const uint32_t aBase = AsAddr + (wr * 16 + (lane & 15)) * A_ROWB + (lane >> 4) * 16;
    const uint32_t bRowOff = (uint32_t)(wc * 128 + ((lane >> 4) << 3) + (lane & 7)) * B_ROWB
                           + (uint32_t)(((lane >> 3) & 1) * 16);

    for (int kc = 0; kc < NKC; kc++) {
        if (kc + 1 < NKC) {
            issueB(kc + 1, (kc + 1) & 1);
            CP_COMMIT();
            CP_WAIT(1);
        } else {
            CP_WAIT(0);
        }
        __syncthreads();      // all threads' chunk data visible

        const uint32_t bChunk = BsAddr + (kc & 1) * SZ_BBUF + bRowOff;
        #pragma unroll
        for (int ks = 0; ks < 2; ks++) {
            const int kk = kc * 2 + ks;
            uint32_t a0, a1, a2, a3;
            asm volatile("ldmatrix.sync.aligned.m8n8.x4.shared.b16 {%0,%1,%2,%3}, [%4];"
                         : "=r"(a0), "=r"(a1), "=r"(a2), "=r"(a3)
                         : "r"(aBase + kk * 32));
            #pragma unroll
            for (int j = 0; j < 8; j++) {
                uint32_t b0, b1, b2, b3;
                asm volatile("ldmatrix.sync.aligned.m8n8.x4.shared.b16 {%0,%1,%2,%3}, [%4];"
                             : "=r"(b0), "=r"(b1), "=r"(b2), "=r"(b3)
                             : "r"(bChunk + j * (16 * B_ROWB) + ks * 32));
                asm volatile("mma.sync.aligned.m16n8k16.row.col.f32.bf16.bf16.f32 "
                             "{%0,%1,%2,%3},{%4,%5,%6,%7},{%8,%9},{%0,%1,%2,%3};"
                             : "+f"(c[2*j][0]), "+f"(c[2*j][1]), "+f"(c[2*j][2]), "+f"(c[2*j][3])
                             : "r"(a0), "r"(a1), "r"(a2), "r"(a3), "r"(b0), "r"(b1));
                asm volatile("mma.sync.aligned.m16n8k16.row.col.f32.bf16.bf16.f32 "
                             "{%0,%1,%2,%3},{%4,%5,%6,%7},{%8,%9},{%0,%1,%2,%3};"
                             : "+f"(c[2*j+1][0]), "+f"(c[2*j+1][1]), "+f"(c[2*j+1][2]), "+f"(c[2*j+1][3])
                             : "r"(a0), "r"(a1), "r"(a2), "r"(a3), "r"(b2), "r"(b3));
            }
        }
        __syncthreads();      // everyone done reading this buffer before reuse
    }

    // ---- epilogue: cos -> dist (in place), masked row sums ----
    const int r0 = wr * 16 + (lane >> 2);       // row within strip (and r0+8)
    float sumlo = 0.0f, sumhi = 0.0f;
    #pragma unroll
    for (int j = 0; j < 16; j++) {
        const int col0 = wc * 128 + (j >> 1) * 16 + (j & 1) * 8 + 2 * (lane & 3);
        #pragma unroll
        for (int e = 0; e < 4; e++)
            c[j][e] = sqrtf(fmaxf(1.0f - c[j][e], 0.0f));
        if (col0 < C_COLS) {                    // col0 even; col0+1 valid iff col0 valid
            sumlo += c[j][0] + c[j][1];
            sumhi += c[j][2] + c[j][3];
        }
    }
    sumlo += __shfl_xor_sync(0xFFFFFFFFu, sumlo, 1);
    sumlo += __shfl_xor_sync(0xFFFFFFFFu, sumlo, 2);
    sumhi += __shfl_xor_sync(0xFFFFFFFFu, sumhi, 1);
    sumhi += __shfl_xor_sync(0xFFFFFFFFu, sumhi, 2);
    if ((lane & 3) == 0) {
        atomicAdd(&rowsum[r0],     sumlo);
        atomicAdd(&rowsum[r0 + 8], sumhi);
    }
    __syncthreads();

    const float sc   = fabsf(dscale[0]);
    const float invT = 1.0f / dtemp[0];
    const float a    = -sc * invT;
    const float meanLo = rowsum[r0]     * (1.0f / (float)C_COLS);
    const float meanHi = rowsum[r0 + 8] * (1.0f / (float)C_COLS);

    float* outLo = out + (size_t)(rowBase + r0)     * C_COLS;
    float* outHi = out + (size_t)(rowBase + r0 + 8) * C_COLS;
    #pragma unroll
    for (int j = 0; j < 16; j++) {
        const int col0 = wc * 128 + (j >> 1) * 16 + (j & 1) * 8 + 2 * (lane & 3);
        if (col0 < C_COLS) {
            float2 lo = make_float2(a * (c[j][0] + meanLo), a * (c[j][1] + meanLo));
            float2 hi = make_float2(a * (c[j][2] + meanHi), a * (c[j][3] + meanHi));
            *(float2*)(outLo + col0) = lo;
            *(float2*)(outHi + col0) = hi;
        }
    }
}

// ---------------------------------------------------------------------------
extern "C" void kernel_launch(void* const* d_in, const int* in_sizes, int n_in,
                              void* d_out, int out_size) {
    const float* feats  = (const float*)d_in[0];   // [32768, 256]
    const float* protos = (const float*)d_in[1];   // [1000, 256]
    const float* dscale = (const float*)d_in[2];   // [1]
    const float* dtemp  = (const float*)d_in[3];   // [1]
    float* out = (float*)d_out;                    // [32768, 1000]

    cudaFuncSetAttribute(dismax_main_kernel,
                         cudaFuncAttributeMaxDynamicSharedMemorySize, SMEM_TOTAL);

    normalize_feats_kernel<<<B_ROWS / 8, 256>>>(feats);
    normalize_protos_kernel<<<C_PAD / 8, 256>>>(protos);
    dismax_main_kernel<<<B_ROWS / BM, 512, SMEM_TOTAL>>>(dscale, dtemp, out);
}